// round 10
// baseline (speedup 1.0000x reference)
#include <cuda_runtime.h>
#include <cuda_fp16.h>
#include <cstdint>

// QuantizedLinearINT4 (sm_103 base target -> legacy mma.sync path).
// Prolog: dequant W(int4 packed)->fp16 g_wh [N,K]; x f32->fp16 g_xh [M,K].
// GEMM: CTA 128x256, 16 warps arranged 2(kK) x 2(M) x 4(N), warp tile 64x64,
//       each warp computes 2 of 4 k16-steps per BK=64 chunk (split-k in chunk),
//       4-stage cp.async pipeline (wait -> sync -> compute -> issue),
//       ldmatrix.x4 feeds, mma.m16n8k16 f32 accum, cross-warpK smem reduction.
// out[M,N] f32 = x @ W^T + bias.

#define KDIM 4096
#define NDIM 11008
#define MDIM 8192
#define BM 128
#define BN 256
#define BK 64                    // halves per k-chunk (128 B rows)
#define NCHUNKS (KDIM / BK)      // 64
#define THREADS 512
#define STAGES 4

#define A_STAGE_BYTES (BM * 128)                      // 16 KB
#define B_STAGE_BYTES (BN * 128)                      // 32 KB
#define STAGE_BYTES (A_STAGE_BYTES + B_STAGE_BYTES)   // 48 KB
#define SMEM_TOTAL (STAGES * STAGE_BYTES)             // 192 KB

#define RED_STRIDE 66            // f32 words per row in reduction buffer

__device__ __half g_xh[(size_t)MDIM * KDIM];   // 64 MB
__device__ __half g_wh[(size_t)NDIM * KDIM];   // 90 MB

// ---------------- prolog kernels ----------------

__global__ void convert_x_kernel(const float* __restrict__ x) {
    size_t i = (size_t)blockIdx.x * blockDim.x + threadIdx.x;  // one float4
    float4 v = ((const float4*)x)[i];
    __half2* o = (__half2*)g_xh;
    o[2 * i]     = __floats2half2_rn(v.x, v.y);
    o[2 * i + 1] = __floats2half2_rn(v.z, v.w);
}

__global__ void dequant_w_kernel(const int* __restrict__ wp,
                                 const float* __restrict__ scales) {
    size_t i = (size_t)blockIdx.x * blockDim.x + threadIdx.x;  // 4 int32 per thread
    size_t base = i * 4;
    int n  = (int)(base >> 11);        // K/2 = 2048 int32 per row
    int k2 = (int)(base & 2047);
    int4 v4 = ((const int4*)wp)[i];
    float s = scales[(n << 5) + (k2 >> 6)];   // 4 int32 never straddle a group
    __half2* o = (__half2*)g_wh + base;
    int vv[4] = {v4.x, v4.y, v4.z, v4.w};
#pragma unroll
    for (int j = 0; j < 4; j++) {
        int v = vv[j];
        float lo = (float)((v & 15) - 8) * s;
        float hi = (float)(((v >> 4) & 15) - 8) * s;
        o[j] = __floats2half2_rn(lo, hi);
    }
}

// ---------------- helpers ----------------

__device__ __forceinline__ uint32_t smem_u32(const void* p) {
    return (uint32_t)__cvta_generic_to_shared(p);
}
__device__ __forceinline__ uint32_t sw128(uint32_t off) {
    return off ^ ((off >> 3) & 0x70);
}
__device__ __forceinline__ void cp_async16(uint32_t saddr, const void* gaddr) {
    asm volatile("cp.async.cg.shared.global [%0], [%1], 16;"
                 :: "r"(saddr), "l"(gaddr));
}
__device__ __forceinline__ void cp_commit() {
    asm volatile("cp.async.commit_group;");
}
template <int N>
__device__ __forceinline__ void cp_wait() {
    asm volatile("cp.async.wait_group %0;" :: "n"(N));
}
__device__ __forceinline__ void ldsm4(uint32_t addr, uint32_t& r0, uint32_t& r1,
                                      uint32_t& r2, uint32_t& r3) {
    asm volatile("ldmatrix.sync.aligned.m8n8.x4.shared.b16 {%0,%1,%2,%3}, [%4];"
                 : "=r"(r0), "=r"(r1), "=r"(r2), "=r"(r3) : "r"(addr));
}
__device__ __forceinline__ void stg64_cs(void* p, float a, float b) {
    asm volatile("st.global.cs.v2.f32 [%0], {%1,%2};" :: "l"(p), "f"(a), "f"(b)
                 : "memory");
}

// ---------------- GEMM kernel ----------------

__global__ __launch_bounds__(THREADS, 1)
void q4_mma_kernel(const float* __restrict__ bias, float* __restrict__ out) {
    extern __shared__ char smem[];
    const uint32_t sbase = smem_u32(smem);

    const int tid  = threadIdx.x;
    const int wid  = tid >> 5;
    const int lane = tid & 31;
    const int g    = lane >> 2;
    const int tig  = lane & 3;
    const int warpK = wid >> 3;          // 0..1: which pair of k16 steps
    const int warpM = (wid >> 2) & 1;    // 0..1: 64 rows each
    const int warpN = wid & 3;           // 0..3: 64 cols each
    const int pos   = wid & 7;           // (warpM, warpN) position id

    const int m0 = blockIdx.x * BM;  // m fastest -> g_xh L2-resident per wave
    const int n0 = blockIdx.y * BN;

    // cp.async mapping: 16B chunks; 512 threads cover 64 rows x 8 segs
    const int crow = tid >> 3;       // 0..63
    const int cseg = tid & 7;        // 16B segment within 128B row
    const __half* aG = g_xh + (size_t)(m0 + crow) * KDIM + cseg * 8;
    const __half* bG = g_wh + (size_t)(n0 + crow) * KDIM + cseg * 8;

    uint32_t aS[2], bS[4];
#pragma unroll
    for (int i = 0; i < 2; i++)
        aS[i] = sw128((uint32_t)((crow + 64 * i) * 128 + cseg * 16));
#pragma unroll
    for (int i = 0; i < 4; i++)
        bS[i] = sw128((uint32_t)((crow + 64 * i) * 128 + cseg * 16));

    auto issue = [&](int kc) {
        const int st = kc % STAGES;
        const uint32_t sa = sbase + st * STAGE_BYTES;
        const uint32_t sb = sa + A_STAGE_BYTES;
        const size_t gofs = (size_t)kc * BK;
#pragma unroll
        for (int i = 0; i < 2; i++)
            cp_async16(sa + aS[i], aG + (size_t)(64 * i) * KDIM + gofs);
#pragma unroll
        for (int i = 0; i < 4; i++)
            cp_async16(sb + bS[i], bG + (size_t)(64 * i) * KDIM + gofs);
    };

    // ldmatrix address components (stage-relative)
    const uint32_t aRow = (uint32_t)(warpM * 64 + (lane & 15));
    const uint32_t aKof = (uint32_t)((lane >> 4) * 16);
    const uint32_t bRow = (uint32_t)(warpN * 64 + ((lane >> 4) << 3) + (lane & 7));
    const uint32_t bKof = (uint32_t)(((lane >> 3) & 1) * 16);
    const uint32_t kBase = (uint32_t)(warpK * 64);   // 2 k16 steps = 64 halves... (2*32B units)

    float acc[4][8][4];
#pragma unroll
    for (int i = 0; i < 4; i++)
#pragma unroll
        for (int j = 0; j < 8; j++)
#pragma unroll
            for (int c = 0; c < 4; c++) acc[i][j][c] = 0.0f;

    // prologue: fill pipeline (one commit group per chunk)
    issue(0); cp_commit();
    issue(1); cp_commit();
    issue(2); cp_commit();

#pragma unroll 1
    for (int kc = 0; kc < NCHUNKS; kc++) {
        cp_wait<2>();
        __syncthreads();            // chunk kc visible; all warps past chunk kc-1

        const int st = kc % STAGES;
        const uint32_t sa = sbase + st * STAGE_BYTES;
        const uint32_t sb = sa + A_STAGE_BYTES;

#pragma unroll
        for (int s = 0; s < 2; s++) {
            const uint32_t koff = kBase + (uint32_t)s * 32;   // bytes within 128B row
            uint32_t a[4][4], b[4][4];
#pragma unroll
            for (int mi = 0; mi < 4; mi++) {
                uint32_t off = (aRow + mi * 16) * 128 + koff + aKof;
                ldsm4(sa + sw128(off), a[mi][0], a[mi][1], a[mi][2], a[mi][3]);
            }
#pragma unroll
            for (int nj = 0; nj < 4; nj++) {
                uint32_t off = (bRow + nj * 16) * 128 + koff + bKof;
                ldsm4(sb + sw128(off), b[nj][0], b[nj][1], b[nj][2], b[nj][3]);
            }
#pragma unroll
            for (int mi = 0; mi < 4; mi++) {
#pragma unroll
                for (int nj = 0; nj < 4; nj++) {
                    asm volatile(
                        "mma.sync.aligned.m16n8k16.row.col.f32.f16.f16.f32 "
                        "{%0,%1,%2,%3}, {%4,%5,%6,%7}, {%8,%9}, {%0,%1,%2,%3};\n"
                        : "+f"(acc[mi][2 * nj][0]), "+f"(acc[mi][2 * nj][1]),
                          "+f"(acc[mi][2 * nj][2]), "+f"(acc[mi][2 * nj][3])
                        : "r"(a[mi][0]), "r"(a[mi][1]), "r"(a[mi][2]), "r"(a[mi][3]),
                          "r"(b[nj][0]), "r"(b[nj][1]));
                    asm volatile(
                        "mma.sync.aligned.m16n8k16.row.col.f32.f16.f16.f32 "
                        "{%0,%1,%2,%3}, {%4,%5,%6,%7}, {%8,%9}, {%0,%1,%2,%3};\n"
                        : "+f"(acc[mi][2 * nj + 1][0]), "+f"(acc[mi][2 * nj + 1][1]),
                          "+f"(acc[mi][2 * nj + 1][2]), "+f"(acc[mi][2 * nj + 1][3])
                        : "r"(a[mi][0]), "r"(a[mi][1]), "r"(a[mi][2]), "r"(a[mi][3]),
                          "r"(b[nj][2]), "r"(b[nj][3]));
                }
            }
        }
        // issue AFTER compute into stage (kc-1)%4 (vacated at the sync above).
        // Commit EVERY iteration (empty group when past the end) so the
        // wait_group<2> arithmetic bounds chunks kc+ at every iteration.
        if (kc + 3 < NCHUNKS) issue(kc + 3);
        cp_commit();
    }

    // ---- cross-warpK reduction + bias + store ----
    __syncthreads();   // stages fully consumed; reuse smem as f32 buffer
    float* red = (float*)smem + (size_t)pos * 64 * RED_STRIDE;

    if (warpK == 1) {
#pragma unroll
        for (int mi = 0; mi < 4; mi++) {
            const int r = mi * 16 + g;
#pragma unroll
            for (int nj = 0; nj < 8; nj++) {
                const int c = nj * 8 + tig * 2;
                *(float2*)(red + r * RED_STRIDE + c) =
                    make_float2(acc[mi][nj][0], acc[mi][nj][1]);
                *(float2*)(red + (r + 8) * RED_STRIDE + c) =
                    make_float2(acc[mi][nj][2], acc[mi][nj][3]);
            }
        }
    }
    __syncthreads();

    if (warpK == 0) {
#pragma unroll
        for (int mi = 0; mi < 4; mi++) {
            const int r = mi * 16 + g;
            const int row = m0 + warpM * 64 + r;
#pragma unroll
            for (int nj = 0; nj < 8; nj++) {
                const int c = nj * 8 + tig * 2;
                const int col = n0 + warpN * 64 + c;
                float2 bb = *(const float2*)(bias + col);
                float2 p0 = *(const float2*)(red + r * RED_STRIDE + c);
                float2 p1 = *(const float2*)(red + (r + 8) * RED_STRIDE + c);
                stg64_cs(out + (size_t)row * NDIM + col,
                         acc[mi][nj][0] + p0.x + bb.x,
                         acc[mi][nj][1] + p0.y + bb.y);
                stg64_cs(out + (size_t)(row + 8) * NDIM + col,
                         acc[mi][nj][2] + p1.x + bb.x,
                         acc[mi][nj][3] + p1.y + bb.y);
            }
        }
    }
}

// ---------------- launcher ----------------

extern "C" void kernel_launch(void* const* d_in, const int* in_sizes, int n_in,
                              void* d_out, int out_size)
{
    const float* x      = (const float*)d_in[0];
    const int*   wp     = (const int*)d_in[1];
    const float* scales = (const float*)d_in[2];
    const float* bias   = (const float*)d_in[3];
    float*       out    = (float*)d_out;

    convert_x_kernel<<<(MDIM * (size_t)KDIM / 4) / 256, 256>>>(x);
    dequant_w_kernel<<<(NDIM * (size_t)(KDIM / 2) / 4) / 256, 256>>>(wp, scales);

    static bool attr_set = false;
    if (!attr_set) {
        cudaFuncSetAttribute(q4_mma_kernel,
                             cudaFuncAttributeMaxDynamicSharedMemorySize, SMEM_TOTAL);
        attr_set = true;
    }
    dim3 grid(MDIM / BM, NDIM / BN);   // (64, 43), m fastest
    q4_mma_kernel<<<grid, THREADS, SMEM_TOTAL>>>(bias, out);
}

// round 11
// speedup vs baseline: 2.6046x; 2.6046x over previous
#include <cuda_runtime.h>
#include <cuda_fp16.h>
#include <cstdint>

// QuantizedLinearINT4 (sm_103 base target -> legacy mma.sync path).
// Prolog (one kernel, block-split): dequant W(int4)->fp16 g_wh; x f32->fp16 g_xh.
// GEMM (R9-proven): CTA 128x256, 16 warps (4x4), warp tile 32x64, BK=64,
//       4-stage cp.async pipeline, one sync per chunk
//       (wait -> sync -> compute -> issue), ldmatrix.x4 feeds,
//       mma.m16n8k16 f32 accum, streaming stores.
// out[M,N] f32 = x @ W^T + bias.

#define KDIM 4096
#define NDIM 11008
#define MDIM 8192
#define BM 128
#define BN 256
#define BK 64                    // halves per k-chunk (128 B rows)
#define NCHUNKS (KDIM / BK)      // 64
#define THREADS 512
#define STAGES 4

#define A_STAGE_BYTES (BM * 128)                      // 16 KB
#define B_STAGE_BYTES (BN * 128)                      // 32 KB
#define STAGE_BYTES (A_STAGE_BYTES + B_STAGE_BYTES)   // 48 KB
#define SMEM_TOTAL (STAGES * STAGE_BYTES)             // 192 KB

__device__ __half g_xh[(size_t)MDIM * KDIM];   // 64 MB
__device__ __half g_wh[(size_t)NDIM * KDIM];   // 90 MB

// ---------------- merged prolog ----------------
// Blocks [0, XBLKS): convert x (8 f32 per thread).
// Blocks [XBLKS, XBLKS+WBLKS): dequant W (4 int32 per thread).

#define XBLKS ((MDIM * (size_t)KDIM / 8) / 256)                 // 16384
#define WBLKS ((NDIM * (size_t)(KDIM / 2) / 4) / 256)           // 22016

__global__ void prolog_kernel(const float* __restrict__ x,
                              const int* __restrict__ wp,
                              const float* __restrict__ scales) {
    if (blockIdx.x < XBLKS) {
        size_t i = (size_t)blockIdx.x * blockDim.x + threadIdx.x;  // 8 floats
        const float4* src = (const float4*)x + 2 * i;
        float4 v0 = src[0];
        float4 v1 = src[1];
        __half2* o = (__half2*)g_xh + 4 * i;
        o[0] = __floats2half2_rn(v0.x, v0.y);
        o[1] = __floats2half2_rn(v0.z, v0.w);
        o[2] = __floats2half2_rn(v1.x, v1.y);
        o[3] = __floats2half2_rn(v1.z, v1.w);
    } else {
        size_t i = (size_t)(blockIdx.x - XBLKS) * blockDim.x + threadIdx.x;
        size_t base = i * 4;                  // int32 index
        int n  = (int)(base >> 11);           // K/2 = 2048 int32 per row
        int k2 = (int)(base & 2047);
        int4 v4 = ((const int4*)wp)[i];
        float s = scales[(n << 5) + (k2 >> 6)];  // 4 int32 never straddle a group
        __half2* o = (__half2*)g_wh + base;
        int vv[4] = {v4.x, v4.y, v4.z, v4.w};
#pragma unroll
        for (int j = 0; j < 4; j++) {
            int v = vv[j];
            float lo = (float)((v & 15) - 8) * s;
            float hi = (float)(((v >> 4) & 15) - 8) * s;
            o[j] = __floats2half2_rn(lo, hi);
        }
    }
}

// ---------------- helpers ----------------

__device__ __forceinline__ uint32_t smem_u32(const void* p) {
    return (uint32_t)__cvta_generic_to_shared(p);
}
__device__ __forceinline__ uint32_t sw128(uint32_t off) {
    return off ^ ((off >> 3) & 0x70);
}
__device__ __forceinline__ void cp_async16(uint32_t saddr, const void* gaddr) {
    asm volatile("cp.async.cg.shared.global [%0], [%1], 16;"
                 :: "r"(saddr), "l"(gaddr));
}
__device__ __forceinline__ void cp_commit() {
    asm volatile("cp.async.commit_group;");
}
template <int N>
__device__ __forceinline__ void cp_wait() {
    asm volatile("cp.async.wait_group %0;" :: "n"(N));
}
__device__ __forceinline__ void ldsm4(uint32_t addr, uint32_t& r0, uint32_t& r1,
                                      uint32_t& r2, uint32_t& r3) {
    asm volatile("ldmatrix.sync.aligned.m8n8.x4.shared.b16 {%0,%1,%2,%3}, [%4];"
                 : "=r"(r0), "=r"(r1), "=r"(r2), "=r"(r3) : "r"(addr));
}
__device__ __forceinline__ void stg64_cs(void* p, float a, float b) {
    asm volatile("st.global.cs.v2.f32 [%0], {%1,%2};" :: "l"(p), "f"(a), "f"(b)
                 : "memory");
}

// ---------------- GEMM kernel (R9) ----------------

__global__ __launch_bounds__(THREADS, 1)
void q4_mma_kernel(const float* __restrict__ bias, float* __restrict__ out) {
    extern __shared__ char smem[];
    const uint32_t sbase = smem_u32(smem);

    const int tid  = threadIdx.x;
    const int wid  = tid >> 5;
    const int lane = tid & 31;
    const int g    = lane >> 2;
    const int tig  = lane & 3;
    const int warpM = wid >> 2;     // 0..3, 32 rows each
    const int warpN = wid & 3;      // 0..3, 64 cols each

    const int m0 = blockIdx.x * BM; // m fastest -> g_xh L2-resident per wave
    const int n0 = blockIdx.y * BN;

    // cp.async mapping: 16B chunks; 512 threads cover 64 rows x 8 segs
    const int crow = tid >> 3;      // 0..63
    const int cseg = tid & 7;       // 16B segment within 128B row
    const __half* aG = g_xh + (size_t)(m0 + crow) * KDIM + cseg * 8;
    const __half* bG = g_wh + (size_t)(n0 + crow) * KDIM + cseg * 8;

    uint32_t aS[2], bS[4];
#pragma unroll
    for (int i = 0; i < 2; i++)
        aS[i] = sw128((uint32_t)((crow + 64 * i) * 128 + cseg * 16));
#pragma unroll
    for (int i = 0; i < 4; i++)
        bS[i] = sw128((uint32_t)((crow + 64 * i) * 128 + cseg * 16));

    auto issue = [&](int kc) {
        const int st = kc % STAGES;
        const uint32_t sa = sbase + st * STAGE_BYTES;
        const uint32_t sb = sa + A_STAGE_BYTES;
        const size_t gofs = (size_t)kc * BK;
#pragma unroll
        for (int i = 0; i < 2; i++)
            cp_async16(sa + aS[i], aG + (size_t)(64 * i) * KDIM + gofs);
#pragma unroll
        for (int i = 0; i < 4; i++)
            cp_async16(sb + bS[i], bG + (size_t)(64 * i) * KDIM + gofs);
        cp_commit();
    };

    // ldmatrix address components (stage-relative)
    const uint32_t aRow = (uint32_t)(warpM * 32 + (lane & 15));
    const uint32_t aKof = (uint32_t)((lane >> 4) * 16);
    const uint32_t bRow = (uint32_t)(warpN * 64 + ((lane >> 4) << 3) + (lane & 7));
    const uint32_t bKof = (uint32_t)(((lane >> 3) & 1) * 16);

    float acc[2][8][4];
#pragma unroll
    for (int i = 0; i < 2; i++)
#pragma unroll
        for (int j = 0; j < 8; j++)
#pragma unroll
            for (int c = 0; c < 4; c++) acc[i][j][c] = 0.0f;

    // prologue: fill pipeline
    issue(0); issue(1); issue(2);

#pragma unroll 1
    for (int kc = 0; kc < NCHUNKS; kc++) {
        cp_wait<2>();
        __syncthreads();            // chunk kc visible; all warps past chunk kc-1

        const int st = kc % STAGES;
        const uint32_t sa = sbase + st * STAGE_BYTES;
        const uint32_t sb = sa + A_STAGE_BYTES;

#pragma unroll
        for (int ks = 0; ks < 4; ks++) {
            uint32_t a[2][4], b[4][4];
#pragma unroll
            for (int mi = 0; mi < 2; mi++) {
                uint32_t off = (aRow + mi * 16) * 128 + ks * 32 + aKof;
                ldsm4(sa + sw128(off), a[mi][0], a[mi][1], a[mi][2], a[mi][3]);
            }
#pragma unroll
            for (int nj = 0; nj < 4; nj++) {
                uint32_t off = (bRow + nj * 16) * 128 + ks * 32 + bKof;
                ldsm4(sb + sw128(off), b[nj][0], b[nj][1], b[nj][2], b[nj][3]);
            }
#pragma unroll
            for (int mi = 0; mi < 2; mi++) {
#pragma unroll
                for (int nj = 0; nj < 4; nj++) {
                    asm volatile(
                        "mma.sync.aligned.m16n8k16.row.col.f32.f16.f16.f32 "
                        "{%0,%1,%2,%3}, {%4,%5,%6,%7}, {%8,%9}, {%0,%1,%2,%3};\n"
                        : "+f"(acc[mi][2 * nj][0]), "+f"(acc[mi][2 * nj][1]),
                          "+f"(acc[mi][2 * nj][2]), "+f"(acc[mi][2 * nj][3])
                        : "r"(a[mi][0]), "r"(a[mi][1]), "r"(a[mi][2]), "r"(a[mi][3]),
                          "r"(b[nj][0]), "r"(b[nj][1]));
                    asm volatile(
                        "mma.sync.aligned.m16n8k16.row.col.f32.f16.f16.f32 "
                        "{%0,%1,%2,%3}, {%4,%5,%6,%7}, {%8,%9}, {%0,%1,%2,%3};\n"
                        : "+f"(acc[mi][2 * nj + 1][0]), "+f"(acc[mi][2 * nj + 1][1]),
                          "+f"(acc[mi][2 * nj + 1][2]), "+f"(acc[mi][2 * nj + 1][3])
                        : "r"(a[mi][0]), "r"(a[mi][1]), "r"(a[mi][2]), "r"(a[mi][3]),
                          "r"(b[nj][2]), "r"(b[nj][3]));
                }
            }
        }
        // issue AFTER compute: contiguous burst while tensor pipe drains;
        // refills stage (kc-1)%4, vacated at the sync above.
        if (kc + 3 < NCHUNKS) issue(kc + 3);
    }

    // ---- epilogue: add bias, write f32 (streaming, evict-first) ----
#pragma unroll
    for (int mi = 0; mi < 2; mi++) {
        const int row = m0 + warpM * 32 + mi * 16 + g;
#pragma unroll
        for (int nj = 0; nj < 8; nj++) {
            const int col = n0 + warpN * 64 + nj * 8 + tig * 2;
            float2 bb = *(const float2*)(bias + col);
            stg64_cs(out + (size_t)row * NDIM + col,
                     acc[mi][nj][0] + bb.x, acc[mi][nj][1] + bb.y);
            stg64_cs(out + (size_t)(row + 8) * NDIM + col,
                     acc[mi][nj][2] + bb.x, acc[mi][nj][3] + bb.y);
        }
    }
}

// ---------------- launcher ----------------

extern "C" void kernel_launch(void* const* d_in, const int* in_sizes, int n_in,
                              void* d_out, int out_size)
{
    const float* x      = (const float*)d_in[0];
    const int*   wp     = (const int*)d_in[1];
    const float* scales = (const float*)d_in[2];
    const float* bias   = (const float*)d_in[3];
    float*       out    = (float*)d_out;

    prolog_kernel<<<(unsigned)(XBLKS + WBLKS), 256>>>(x, wp, scales);

    static bool attr_set = false;
    if (!attr_set) {
        cudaFuncSetAttribute(q4_mma_kernel,
                             cudaFuncAttributeMaxDynamicSharedMemorySize, SMEM_TOTAL);
        attr_set = true;
    }
    dim3 grid(MDIM / BM, NDIM / BN);   // (64, 43), m fastest
    q4_mma_kernel<<<grid, THREADS, SMEM_TOTAL>>>(bias, out);
}

// round 13
// speedup vs baseline: 2.7927x; 1.0722x over previous
#include <cuda_runtime.h>
#include <cuda_fp16.h>
#include <cstdint>

// QuantizedLinearINT4 (sm_103 base target -> legacy mma.sync path).
// Prolog (one kernel, block-split): dequant W(int4)->fp16 g_wh; x f32->fp16 g_xh.
// GEMM: CTA 128x128, 8 warps (4x2), warp tile 32x64, BK=64,
//       3-stage cp.async pipeline, 96KB smem -> 2 CTAs/SM for cross-CTA overlap,
//       one sync per chunk (wait -> sync -> compute -> issue), ldmatrix.x4,
//       mma.m16n8k16 f32 accum, streaming stores.
// out[M,N] f32 = x @ W^T + bias.

#define KDIM 4096
#define NDIM 11008
#define MDIM 8192
#define BM 128
#define BN 128
#define BK 64                    // halves per k-chunk (128 B rows)
#define NCHUNKS (KDIM / BK)      // 64
#define THREADS 256
#define STAGES 3

#define A_STAGE_BYTES (BM * 128)                      // 16 KB
#define B_STAGE_BYTES (BN * 128)                      // 16 KB
#define STAGE_BYTES (A_STAGE_BYTES + B_STAGE_BYTES)   // 32 KB
#define SMEM_TOTAL (STAGES * STAGE_BYTES)             // 96 KB -> 2 CTAs/SM

__device__ __half g_xh[(size_t)MDIM * KDIM];   // 64 MB
__device__ __half g_wh[(size_t)NDIM * KDIM];   // 90 MB

// ---------------- merged prolog ----------------
// Blocks [0, XBLKS): convert x (8 f32 per thread).
// Blocks [XBLKS, XBLKS+WBLKS): dequant W (4 int32 per thread).

#define XBLKS ((MDIM * (size_t)KDIM / 8) / 256)                 // 16384
#define WBLKS ((NDIM * (size_t)(KDIM / 2) / 4) / 256)           // 22016

__global__ void prolog_kernel(const float* __restrict__ x,
                              const int* __restrict__ wp,
                              const float* __restrict__ scales) {
    if (blockIdx.x < XBLKS) {
        size_t i = (size_t)blockIdx.x * blockDim.x + threadIdx.x;  // 8 floats
        const float4* src = (const float4*)x + 2 * i;
        float4 v0 = src[0];
        float4 v1 = src[1];
        __half2* o = (__half2*)g_xh + 4 * i;
        o[0] = __floats2half2_rn(v0.x, v0.y);
        o[1] = __floats2half2_rn(v0.z, v0.w);
        o[2] = __floats2half2_rn(v1.x, v1.y);
        o[3] = __floats2half2_rn(v1.z, v1.w);
    } else {
        size_t i = (size_t)(blockIdx.x - XBLKS) * blockDim.x + threadIdx.x;
        size_t base = i * 4;                  // int32 index
        int n  = (int)(base >> 11);           // K/2 = 2048 int32 per row
        int k2 = (int)(base & 2047);
        int4 v4 = ((const int4*)wp)[i];
        float s = scales[(n << 5) + (k2 >> 6)];  // 4 int32 never straddle a group
        __half2* o = (__half2*)g_wh + base;
        int vv[4] = {v4.x, v4.y, v4.z, v4.w};
#pragma unroll
        for (int j = 0; j < 4; j++) {
            int v = vv[j];
            float lo = (float)((v & 15) - 8) * s;
            float hi = (float)(((v >> 4) & 15) - 8) * s;
            o[j] = __floats2half2_rn(lo, hi);
        }
    }
}

// ---------------- helpers ----------------

__device__ __forceinline__ uint32_t smem_u32(const void* p) {
    return (uint32_t)__cvta_generic_to_shared(p);
}
__device__ __forceinline__ uint32_t sw128(uint32_t off) {
    return off ^ ((off >> 3) & 0x70);
}
__device__ __forceinline__ void cp_async16(uint32_t saddr, const void* gaddr) {
    asm volatile("cp.async.cg.shared.global [%0], [%1], 16;"
                 :: "r"(saddr), "l"(gaddr));
}
__device__ __forceinline__ void cp_commit() {
    asm volatile("cp.async.commit_group;");
}
template <int N>
__device__ __forceinline__ void cp_wait() {
    asm volatile("cp.async.wait_group %0;" :: "n"(N));
}
__device__ __forceinline__ void ldsm4(uint32_t addr, uint32_t& r0, uint32_t& r1,
                                      uint32_t& r2, uint32_t& r3) {
    asm volatile("ldmatrix.sync.aligned.m8n8.x4.shared.b16 {%0,%1,%2,%3}, [%4];"
                 : "=r"(r0), "=r"(r1), "=r"(r2), "=r"(r3) : "r"(addr));
}
__device__ __forceinline__ void stg64_cs(void* p, float a, float b) {
    asm volatile("st.global.cs.v2.f32 [%0], {%1,%2};" :: "l"(p), "f"(a), "f"(b)
                 : "memory");
}

// ---------------- GEMM kernel ----------------

__global__ __launch_bounds__(THREADS, 2)
void q4_mma_kernel(const float* __restrict__ bias, float* __restrict__ out) {
    extern __shared__ char smem[];
    const uint32_t sbase = smem_u32(smem);

    const int tid  = threadIdx.x;
    const int wid  = tid >> 5;
    const int lane = tid & 31;
    const int g    = lane >> 2;
    const int tig  = lane & 3;
    const int warpM = wid >> 1;     // 0..3, 32 rows each
    const int warpN = wid & 1;      // 0..1, 64 cols each

    const int m0 = blockIdx.x * BM; // m fastest -> g_xh L2-resident per wave
    const int n0 = blockIdx.y * BN;

    // cp.async mapping: 16B chunks; 256 threads cover 32 rows x 8 segs per step
    const int crow = tid >> 3;      // 0..31
    const int cseg = tid & 7;       // 16B segment within 128B row
    const __half* aG = g_xh + (size_t)(m0 + crow) * KDIM + cseg * 8;
    const __half* bG = g_wh + (size_t)(n0 + crow) * KDIM + cseg * 8;

    uint32_t cS[4];
#pragma unroll
    for (int i = 0; i < 4; i++)
        cS[i] = sw128((uint32_t)((crow + 32 * i) * 128 + cseg * 16));

    auto issue = [&](int kc) {
        const int st = kc % STAGES;
        const uint32_t sa = sbase + st * STAGE_BYTES;
        const uint32_t sb = sa + A_STAGE_BYTES;
        const size_t gofs = (size_t)kc * BK;
#pragma unroll
        for (int i = 0; i < 4; i++)
            cp_async16(sa + cS[i], aG + (size_t)(32 * i) * KDIM + gofs);
#pragma unroll
        for (int i = 0; i < 4; i++)
            cp_async16(sb + cS[i], bG + (size_t)(32 * i) * KDIM + gofs);
        cp_commit();
    };

    // ldmatrix address components (stage-relative)
    const uint32_t aRow = (uint32_t)(warpM * 32 + (lane & 15));
    const uint32_t aKof = (uint32_t)((lane >> 4) * 16);
    const uint32_t bRow = (uint32_t)(warpN * 64 + ((lane >> 4) << 3) + (lane & 7));
    const uint32_t bKof = (uint32_t)(((lane >> 3) & 1) * 16);

    // acc[mi][j]: j = half*4 + nj*2 + h, where half in {0,1} selects cols +0/+32,
    // nj in {0,1} the n16 tile within the half, h the n8 half of the n16 tile.
    // Column offset of j: (j<4 ? 0:32) + ((j&3)>>1)*16 + (j&1)*8.
    float acc[2][8][4];
#pragma unroll
    for (int i = 0; i < 2; i++)
#pragma unroll
        for (int j = 0; j < 8; j++)
#pragma unroll
            for (int c = 0; c < 4; c++) acc[i][j][c] = 0.0f;

    // prologue: fill pipeline (3 stages -> 2 ahead)
    issue(0); issue(1);

#pragma unroll 1
    for (int kc = 0; kc < NCHUNKS; kc++) {
        cp_wait<1>();
        __syncthreads();            // chunk kc visible; all warps past chunk kc-1

        const int st = kc % STAGES;
        const uint32_t sa = sbase + st * STAGE_BYTES;
        const uint32_t sb = sa + A_STAGE_BYTES;

#pragma unroll
        for (int half = 0; half < 2; half++) {
            const uint32_t colBase = (uint32_t)(half * 32);
#pragma unroll
            for (int ks = 0; ks < 4; ks++) {
                uint32_t a[2][4], b[2][4];
#pragma unroll
                for (int mi = 0; mi < 2; mi++) {
                    uint32_t off = (aRow + mi * 16) * 128 + ks * 32 + aKof;
                    ldsm4(sa + sw128(off), a[mi][0], a[mi][1], a[mi][2], a[mi][3]);
                }
#pragma unroll
                for (int nj = 0; nj < 2; nj++) {
                    uint32_t off = (bRow + colBase + nj * 16) * 128 + ks * 32 + bKof;
                    ldsm4(sb + sw128(off), b[nj][0], b[nj][1], b[nj][2], b[nj][3]);
                }
#pragma unroll
                for (int mi = 0; mi < 2; mi++) {
#pragma unroll
                    for (int nj = 0; nj < 2; nj++) {
                        const int j0 = half * 4 + nj * 2;
                        asm volatile(
                            "mma.sync.aligned.m16n8k16.row.col.f32.f16.f16.f32 "
                            "{%0,%1,%2,%3}, {%4,%5,%6,%7}, {%8,%9}, {%0,%1,%2,%3};\n"
                            : "+f"(acc[mi][j0][0]), "+f"(acc[mi][j0][1]),
                              "+f"(acc[mi][j0][2]), "+f"(acc[mi][j0][3])
                            : "r"(a[mi][0]), "r"(a[mi][1]), "r"(a[mi][2]), "r"(a[mi][3]),
                              "r"(b[nj][0]), "r"(b[nj][1]));
                        asm volatile(
                            "mma.sync.aligned.m16n8k16.row.col.f32.f16.f16.f32 "
                            "{%0,%1,%2,%3}, {%4,%5,%6,%7}, {%8,%9}, {%0,%1,%2,%3};\n"
                            : "+f"(acc[mi][j0 + 1][0]), "+f"(acc[mi][j0 + 1][1]),
                              "+f"(acc[mi][j0 + 1][2]), "+f"(acc[mi][j0 + 1][3])
                            : "r"(a[mi][0]), "r"(a[mi][1]), "r"(a[mi][2]), "r"(a[mi][3]),
                              "r"(b[nj][2]), "r"(b[nj][3]));
                    }
                }
            }
        }
        // issue AFTER compute into stage (kc+2)%3 == (kc-1)%3, vacated above.
        if (kc + 2 < NCHUNKS) issue(kc + 2);
    }

    // ---- epilogue: add bias, write f32 (streaming, evict-first) ----
#pragma unroll
    for (int mi = 0; mi < 2; mi++) {
        const int row = m0 + warpM * 32 + mi * 16 + g;
#pragma unroll
        for (int j = 0; j < 8; j++) {
            const int base = (j < 4 ? 0 : 32) + ((j & 3) >> 1) * 16 + (j & 1) * 8;
            const int col = n0 + warpN * 64 + base + tig * 2;
            float2 bb = *(const float2*)(bias + col);
            stg64_cs(out + (size_t)row * NDIM + col,
                     acc[mi][j][0] + bb.x, acc[mi][j][1] + bb.y);
            stg64_cs(out + (size_t)(row + 8) * NDIM + col,
                     acc[mi][j][2] + bb.x, acc[mi][j][3] + bb.y);
        }
    }
}

// ---------------- launcher ----------------

extern "C" void kernel_launch(void* const* d_in, const int* in_sizes, int n_in,
                              void* d_out, int out_size)
{
    const float* x      = (const float*)d_in[0];
    const int*   wp     = (const int*)d_in[1];
    const float* scales = (const float*)d_in[2];
    const float* bias   = (const float*)d_in[3];
    float*       out    = (float*)d_out;

    prolog_kernel<<<(unsigned)(XBLKS + WBLKS), 256>>>(x, wp, scales);

    static bool attr_set = false;
    if (!attr_set) {
        cudaFuncSetAttribute(q4_mma_kernel,
                             cudaFuncAttributeMaxDynamicSharedMemorySize, SMEM_TOTAL);
        attr_set = true;
    }
    dim3 grid(MDIM / BM, NDIM / BN);   // (64, 86), m fastest
    q4_mma_kernel<<<grid, THREADS, SMEM_TOTAL>>>(bias, out);
}

// round 17
// speedup vs baseline: 2.7982x; 1.0020x over previous
#include <cuda_runtime.h>
#include <cuda_fp16.h>
#include <cstdint>

// QuantizedLinearINT4 (sm_103 base target -> legacy mma.sync path).
// Prolog (one kernel, block-split): dequant W(int4)->fp16 g_wh; x f32->fp16 g_xh.
// GEMM: CTA 128x128, 8 warps (4x2), warp tile 32x64, BK=64,
//       3-stage cp.async pipeline, 96KB smem -> 2 CTAs/SM,
//       one sync per chunk (wait -> sync -> compute -> issue), ldmatrix.x4,
//       mma.m16n8k16 f32 accum, fp16-rounded epilogue, streaming stores.
// RACE FIX (root cause of all rel_err drift): cp.async commit_group is executed
// UNCONDITIONALLY every mainloop iteration (empty groups in the tail), so
// cp_wait<1> provably covers the current chunk at EVERY kc including the last.
// out[M,N] f32 = f32(fp16(x @ W^T + bias)).

#define KDIM 4096
#define NDIM 11008
#define MDIM 8192
#define BM 128
#define BN 128
#define BK 64                    // halves per k-chunk (128 B rows)
#define NCHUNKS (KDIM / BK)      // 64
#define THREADS 256
#define STAGES 3

#define A_STAGE_BYTES (BM * 128)                      // 16 KB
#define B_STAGE_BYTES (BN * 128)                      // 16 KB
#define STAGE_BYTES (A_STAGE_BYTES + B_STAGE_BYTES)   // 32 KB
#define SMEM_TOTAL (STAGES * STAGE_BYTES)             // 96 KB -> 2 CTAs/SM

__device__ __half g_xh[(size_t)MDIM * KDIM];   // 64 MB
__device__ __half g_wh[(size_t)NDIM * KDIM];   // 90 MB

// ---------------- merged prolog ----------------
// Blocks [0, XBLKS): convert x (8 f32 per thread).
// Blocks [XBLKS, XBLKS+WBLKS): dequant W (4 int32 per thread).

#define XBLKS ((MDIM * (size_t)KDIM / 8) / 256)                 // 16384
#define WBLKS ((NDIM * (size_t)(KDIM / 2) / 4) / 256)           // 22016

__global__ void prolog_kernel(const float* __restrict__ x,
                              const int* __restrict__ wp,
                              const float* __restrict__ scales) {
    if (blockIdx.x < XBLKS) {
        size_t i = (size_t)blockIdx.x * blockDim.x + threadIdx.x;  // 8 floats
        const float4* src = (const float4*)x + 2 * i;
        float4 v0 = src[0];
        float4 v1 = src[1];
        __half2* o = (__half2*)g_xh + 4 * i;
        o[0] = __floats2half2_rn(v0.x, v0.y);
        o[1] = __floats2half2_rn(v0.z, v0.w);
        o[2] = __floats2half2_rn(v1.x, v1.y);
        o[3] = __floats2half2_rn(v1.z, v1.w);
    } else {
        size_t i = (size_t)(blockIdx.x - XBLKS) * blockDim.x + threadIdx.x;
        size_t base = i * 4;                  // int32 index
        int n  = (int)(base >> 11);           // K/2 = 2048 int32 per row
        int k2 = (int)(base & 2047);
        int4 v4 = ((const int4*)wp)[i];
        float s = scales[(n << 5) + (k2 >> 6)];  // 4 int32 never straddle a group
        __half2* o = (__half2*)g_wh + base;
        int vv[4] = {v4.x, v4.y, v4.z, v4.w};
#pragma unroll
        for (int j = 0; j < 4; j++) {
            int v = vv[j];
            float lo = (float)((v & 15) - 8) * s;
            float hi = (float)(((v >> 4) & 15) - 8) * s;
            o[j] = __floats2half2_rn(lo, hi);
        }
    }
}

// ---------------- helpers ----------------

__device__ __forceinline__ uint32_t smem_u32(const void* p) {
    return (uint32_t)__cvta_generic_to_shared(p);
}
__device__ __forceinline__ uint32_t sw128(uint32_t off) {
    return off ^ ((off >> 3) & 0x70);
}
__device__ __forceinline__ void cp_async16(uint32_t saddr, const void* gaddr) {
    asm volatile("cp.async.cg.shared.global [%0], [%1], 16;"
                 :: "r"(saddr), "l"(gaddr));
}
__device__ __forceinline__ void cp_commit() {
    asm volatile("cp.async.commit_group;");
}
template <int N>
__device__ __forceinline__ void cp_wait() {
    asm volatile("cp.async.wait_group %0;" :: "n"(N));
}
__device__ __forceinline__ void ldsm4(uint32_t addr, uint32_t& r0, uint32_t& r1,
                                      uint32_t& r2, uint32_t& r3) {
    asm volatile("ldmatrix.sync.aligned.m8n8.x4.shared.b16 {%0,%1,%2,%3}, [%4];"
                 : "=r"(r0), "=r"(r1), "=r"(r2), "=r"(r3) : "r"(addr));
}
__device__ __forceinline__ void stg64_cs(void* p, float a, float b) {
    asm volatile("st.global.cs.v2.f32 [%0], {%1,%2};" :: "l"(p), "f"(a), "f"(b)
                 : "memory");
}
// Round to fp16 and back to f32 — matches the reference's output dtype.
__device__ __forceinline__ float h16(float v) {
    return __half2float(__float2half_rn(v));
}

// ---------------- GEMM kernel ----------------

__global__ __launch_bounds__(THREADS, 2)
void q4_mma_kernel(const float* __restrict__ bias, float* __restrict__ out) {
    extern __shared__ char smem[];
    const uint32_t sbase = smem_u32(smem);

    const int tid  = threadIdx.x;
    const int wid  = tid >> 5;
    const int lane = tid & 31;
    const int g    = lane >> 2;
    const int tig  = lane & 3;
    const int warpM = wid >> 1;     // 0..3, 32 rows each
    const int warpN = wid & 1;      // 0..1, 64 cols each

    const int m0 = blockIdx.x * BM; // m fastest -> g_xh L2-resident per wave
    const int n0 = blockIdx.y * BN;

    // cp.async mapping: 16B chunks; 256 threads cover 32 rows x 8 segs per step
    const int crow = tid >> 3;      // 0..31
    const int cseg = tid & 7;       // 16B segment within 128B row
    const __half* aG = g_xh + (size_t)(m0 + crow) * KDIM + cseg * 8;
    const __half* bG = g_wh + (size_t)(n0 + crow) * KDIM + cseg * 8;

    uint32_t cS[4];
#pragma unroll
    for (int i = 0; i < 4; i++)
        cS[i] = sw128((uint32_t)((crow + 32 * i) * 128 + cseg * 16));

    // NOTE: no commit inside issue(); the mainloop commits unconditionally.
    auto issue = [&](int kc) {
        const int st = kc % STAGES;
        const uint32_t sa = sbase + st * STAGE_BYTES;
        const uint32_t sb = sa + A_STAGE_BYTES;
        const size_t gofs = (size_t)kc * BK;
#pragma unroll
        for (int i = 0; i < 4; i++)
            cp_async16(sa + cS[i], aG + (size_t)(32 * i) * KDIM + gofs);
#pragma unroll
        for (int i = 0; i < 4; i++)
            cp_async16(sb + cS[i], bG + (size_t)(32 * i) * KDIM + gofs);
    };

    // ldmatrix address components (stage-relative)
    const uint32_t aRow = (uint32_t)(warpM * 32 + (lane & 15));
    const uint32_t aKof = (uint32_t)((lane >> 4) * 16);
    const uint32_t bRow = (uint32_t)(warpN * 64 + ((lane >> 4) << 3) + (lane & 7));
    const uint32_t bKof = (uint32_t)(((lane >> 3) & 1) * 16);

    // acc[mi][j]: j = half*4 + nj*2 + h; column offset of j:
    //   (j<4 ? 0:32) + ((j&3)>>1)*16 + (j&1)*8.
    float acc[2][8][4];
#pragma unroll
    for (int i = 0; i < 2; i++)
#pragma unroll
        for (int j = 0; j < 8; j++)
#pragma unroll
            for (int c = 0; c < 4; c++) acc[i][j][c] = 0.0f;

    // prologue: fill pipeline (3 stages -> 2 ahead), one group per chunk
    issue(0); cp_commit();
    issue(1); cp_commit();

#pragma unroll 1
    for (int kc = 0; kc < NCHUNKS; kc++) {
        // Groups committed so far: chunks 0..kc+1 (tail iterations commit
        // empty groups, keeping the count). wait<1> -> chunks 0..kc landed.
        cp_wait<1>();
        __syncthreads();            // chunk kc visible; all warps past chunk kc-1

        const int st = kc % STAGES;
        const uint32_t sa = sbase + st * STAGE_BYTES;
        const uint32_t sb = sa + A_STAGE_BYTES;

#pragma unroll
        for (int half = 0; half < 2; half++) {
            const uint32_t colBase = (uint32_t)(half * 32);
#pragma unroll
            for (int ks = 0; ks < 4; ks++) {
                uint32_t a[2][4], b[2][4];
#pragma unroll
                for (int mi = 0; mi < 2; mi++) {
                    uint32_t off = (aRow + mi * 16) * 128 + ks * 32 + aKof;
                    ldsm4(sa + sw128(off), a[mi][0], a[mi][1], a[mi][2], a[mi][3]);
                }
#pragma unroll
                for (int nj = 0; nj < 2; nj++) {
                    uint32_t off = (bRow + colBase + nj * 16) * 128 + ks * 32 + bKof;
                    ldsm4(sb + sw128(off), b[nj][0], b[nj][1], b[nj][2], b[nj][3]);
                }
#pragma unroll
                for (int mi = 0; mi < 2; mi++) {
#pragma unroll
                    for (int nj = 0; nj < 2; nj++) {
                        const int j0 = half * 4 + nj * 2;
                        asm volatile(
                            "mma.sync.aligned.m16n8k16.row.col.f32.f16.f16.f32 "
                            "{%0,%1,%2,%3}, {%4,%5,%6,%7}, {%8,%9}, {%0,%1,%2,%3};\n"
                            : "+f"(acc[mi][j0][0]), "+f"(acc[mi][j0][1]),
                              "+f"(acc[mi][j0][2]), "+f"(acc[mi][j0][3])
                            : "r"(a[mi][0]), "r"(a[mi][1]), "r"(a[mi][2]), "r"(a[mi][3]),
                              "r"(b[nj][0]), "r"(b[nj][1]));
                        asm volatile(
                            "mma.sync.aligned.m16n8k16.row.col.f32.f16.f16.f32 "
                            "{%0,%1,%2,%3}, {%4,%5,%6,%7}, {%8,%9}, {%0,%1,%2,%3};\n"
                            : "+f"(acc[mi][j0 + 1][0]), "+f"(acc[mi][j0 + 1][1]),
                              "+f"(acc[mi][j0 + 1][2]), "+f"(acc[mi][j0 + 1][3])
                            : "r"(a[mi][0]), "r"(a[mi][1]), "r"(a[mi][2]), "r"(a[mi][3]),
                              "r"(b[nj][2]), "r"(b[nj][3]));
                    }
                }
            }
        }
        // issue AFTER compute into stage (kc+2)%3 == (kc-1)%3 (vacated above).
        // Commit EVERY iteration so the wait<1> arithmetic holds in the tail.
        if (kc + 2 < NCHUNKS) issue(kc + 2);
        cp_commit();
    }

    // ---- epilogue: add bias, round to fp16 (reference output dtype), write f32 ----
#pragma unroll
    for (int mi = 0; mi < 2; mi++) {
        const int row = m0 + warpM * 32 + mi * 16 + g;
#pragma unroll
        for (int j = 0; j < 8; j++) {
            const int base = (j < 4 ? 0 : 32) + ((j & 3) >> 1) * 16 + (j & 1) * 8;
            const int col = n0 + warpN * 64 + base + tig * 2;
            float2 bb = *(const float2*)(bias + col);
            stg64_cs(out + (size_t)row * NDIM + col,
                     h16(acc[mi][j][0] + bb.x), h16(acc[mi][j][1] + bb.y));
            stg64_cs(out + (size_t)(row + 8) * NDIM + col,
                     h16(acc[mi][j][2] + bb.x), h16(acc[mi][j][3] + bb.y));
        }
    }
}

// ---------------- launcher ----------------

extern "C" void kernel_launch(void* const* d_in, const int* in_sizes, int n_in,
                              void* d_out, int out_size)
{
    const float* x      = (const float*)d_in[0];
    const int*   wp     = (const int*)d_in[1];
    const float* scales = (const float*)d_in[2];
    const float* bias   = (const float*)d_in[3];
    float*       out    = (float*)d_out;

    prolog_kernel<<<(unsigned)(XBLKS + WBLKS), 256>>>(x, wp, scales);

    static bool attr_set = false;
    if (!attr_set) {
        cudaFuncSetAttribute(q4_mma_kernel,
                             cudaFuncAttributeMaxDynamicSharedMemorySize, SMEM_TOTAL);
        attr_set = true;
    }
    dim3 grid(MDIM / BM, NDIM / BN);   // (64, 86), m fastest
    q4_mma_kernel<<<grid, THREADS, SMEM_TOTAL>>>(bias, out);
}